// round 8
// baseline (speedup 1.0000x reference)
#include <cuda_runtime.h>
#include <cuda.h>
#include <cstdint>

// ============================================================
// QuantizedConv2d exact int conv via split-weight int8 mma.sync GEMM
//   x[8,128,56,56], w[256,128,3,3], bias[256], shift=16 (structural)
//   out[8,256,56,56] = (conv(x,w)+bias) >> 16
// w = (w>>8)*256 + (w&255): hi plane s8, lo plane u8; two s32 GEMMs,
// recombined in i64. Bit-exact.
// NHWC repack with zero halo + implicit im2col GEMM (K = (kh,kw,cin)).
// R7: deeper pipeline was ~neutral (tensor stuck 43%). This round: KC=128
// (one full (kh,kw) tap per chunk) -> 9 chunks, half the barriers, 64 MMAs
// per warp per sync, pitch-144 smem (conflict-free LDSM), 3-stage cp.async.
// Also: warp-parallel dtype detection.
// ============================================================

static constexpr int NB    = 8;
static constexpr int CIN   = 128;
static constexpr int COUT  = 256;
static constexpr int HW    = 56;
static constexpr int HW2   = HW * HW;           // 3136
static constexpr int NPIX  = NB * HW2;          // 25088
static constexpr int KDIM  = CIN * 9;           // 1152
static constexpr int SHIFT = 16;
static constexpr int PHW   = HW + 2;            // 58 (padded)

static constexpr int CTA_M = 128;               // pixels
static constexpr int CTA_N = 128;               // couts
static constexpr int KC    = 128;               // K chunk = full cin of one tap
static constexpr int NCHUNK = KDIM / KC;        // 9
static constexpr int M_TILES = NPIX / CTA_M;    // 196
static constexpr int N_TILES = COUT / CTA_N;    // 2
static constexpr int THREADS = 512;             // 16 warps: 4(M) x 4(N)

static constexpr int STAGES  = 3;
static constexpr int PITCH   = 144;             // 36 words: LDSM conflict-free
static constexpr int SM_TILE = 128 * PITCH;     // 18432
static constexpr int SM_STAGE = 3 * SM_TILE;    // 55296 (A, Bhi, Blo)
static constexpr int SM_TOTAL = STAGES * SM_STAGE;  // 165888

static constexpr int FLAG_I64 = 0, FLAG_I32 = 1, FLAG_F32 = 2, FLAG_F64 = 3;

// ---------------- scratch (device globals; allocation-free) ----------------
__device__ __align__(128) int8_t g_Xt[(size_t)NB * PHW * PHW * CIN];  // 3.44MB
__device__ __align__(128) int8_t g_W[2 * (size_t)COUT * KDIM];        // hi|lo planes
__device__ int g_flag;

// ---------------- PTX helpers ----------------
__device__ __forceinline__ uint32_t smem_to_u32(const void* p) {
    uint32_t a;
    asm("{ .reg .u64 t; cvta.to.shared.u64 t, %1; cvt.u32.u64 %0, t; }" : "=r"(a) : "l"(p));
    return a;
}
__device__ __forceinline__ void cp16(uint32_t dst, const void* src) {
    asm volatile("cp.async.cg.shared.global [%0], [%1], 16;" :: "r"(dst), "l"(src));
}
#define CP_COMMIT() asm volatile("cp.async.commit_group;" ::: "memory")
#define CP_WAIT(n)  asm volatile("cp.async.wait_group %0;" :: "n"(n) : "memory")

__device__ __forceinline__ void ldsm_x4(uint32_t* r, uint32_t addr) {
    asm volatile("ldmatrix.sync.aligned.m8n8.x4.shared.b16 {%0,%1,%2,%3}, [%4];"
                 : "=r"(r[0]), "=r"(r[1]), "=r"(r[2]), "=r"(r[3]) : "r"(addr));
}
__device__ __forceinline__ void mma_s8s8(int* c, const uint32_t* a, const uint32_t* b) {
    asm volatile("mma.sync.aligned.m16n8k32.row.col.s32.s8.s8.s32 "
                 "{%0,%1,%2,%3}, {%4,%5,%6,%7}, {%8,%9}, {%0,%1,%2,%3};"
                 : "+r"(c[0]), "+r"(c[1]), "+r"(c[2]), "+r"(c[3])
                 : "r"(a[0]), "r"(a[1]), "r"(a[2]), "r"(a[3]), "r"(b[0]), "r"(b[1]));
}
__device__ __forceinline__ void mma_s8u8(int* c, const uint32_t* a, const uint32_t* b) {
    asm volatile("mma.sync.aligned.m16n8k32.row.col.s32.s8.u8.s32 "
                 "{%0,%1,%2,%3}, {%4,%5,%6,%7}, {%8,%9}, {%0,%1,%2,%3};"
                 : "+r"(c[0]), "+r"(c[1]), "+r"(c[2]), "+r"(c[3])
                 : "r"(a[0]), "r"(a[1]), "r"(a[2]), "r"(a[3]), "r"(b[0]), "r"(b[1]));
}

// ---------------- dtype detection (warp-parallel) ----------------
__global__ void detect_kernel(const void* xraw) {
    if (blockIdx.x != 0) return;
    int lane = threadIdx.x & 31;
    const int* w = (const int*)xraw;
    int signext = 0, small = 0, lozero = 0;
#pragma unroll
    for (int j = 0; j < 4; j++) {
        int i = lane + j * 32;
        int lo = w[2 * i], hi = w[2 * i + 1];
        if (hi == (lo < 0 ? -1 : 0)) signext++;
        if (lo >= -256 && lo < 256 && hi >= -256 && hi < 256) small++;
        if (lo == 0) lozero++;
    }
#pragma unroll
    for (int off = 16; off > 0; off >>= 1) {
        signext += __shfl_down_sync(0xffffffffu, signext, off);
        small   += __shfl_down_sync(0xffffffffu, small,   off);
        lozero  += __shfl_down_sync(0xffffffffu, lozero,  off);
    }
    if (lane == 0) {
        int f;
        if (signext >= 120)      f = FLAG_I64;
        else if (small >= 120)   f = FLAG_I32;
        else if (lozero >= 100)  f = FLAG_F64;
        else                     f = FLAG_F32;
        g_flag = f;
    }
}

__device__ __forceinline__ long long load_val(const void* p, size_t idx, int flag) {
    if (flag == FLAG_I64) return ((const long long*)p)[idx];
    if (flag == FLAG_I32) return (long long)((const int*)p)[idx];
    if (flag == FLAG_F64) return __double2ll_rn(((const double*)p)[idx]);
    return (long long)__float2ll_rn(((const float*)p)[idx]);
}

// ---------------- kernel 1: pack + NCHW->NHWC transpose with halo ----------------
__global__ void __launch_bounds__(256)
transpose_kernel(const void* __restrict__ x) {
    __shared__ int8_t s[CIN * (HW + 1)];   // pitch 57 to dodge bank conflicts
    int b  = blockIdx.x;
    int n  = b / PHW;
    int ph = b - n * PHW;
    int8_t* dst = g_Xt + ((size_t)(n * PHW + ph) * PHW) * CIN;
    int t = threadIdx.x;

    if (ph == 0 || ph == PHW - 1) {
        for (int i = t; i < PHW * CIN / 4; i += 256) ((int*)dst)[i] = 0;
        return;
    }
    int h = ph - 1;
    const int flag = g_flag;
    for (int i = t; i < CIN * HW; i += 256) {
        int c = i / HW, w = i - c * HW;
        long long v = load_val(x, ((size_t)(n * CIN + c) * HW + h) * HW + w, flag);
        s[c * (HW + 1) + w] = (int8_t)v;
    }
    __syncthreads();
    for (int i = t; i < PHW * (CIN / 4); i += 256) {
        int pw = i >> 5;              // 0..57
        int c0 = (i & 31) * 4;
        uint32_t word = 0;
        if (pw >= 1 && pw <= HW) {
            int w = pw - 1;
            uchar4 u;
            u.x = (uint8_t)s[(c0 + 0) * (HW + 1) + w];
            u.y = (uint8_t)s[(c0 + 1) * (HW + 1) + w];
            u.z = (uint8_t)s[(c0 + 2) * (HW + 1) + w];
            u.w = (uint8_t)s[(c0 + 3) * (HW + 1) + w];
            word = *(uint32_t*)&u;
        }
        ((uint32_t*)dst)[i] = word;
    }
}

// ---------------- kernel 2: weight planes, K reordered to (khkw, cin) ----------------
__global__ void prepw_kernel(const void* __restrict__ wq) {
    int idx = blockIdx.x * blockDim.x + threadIdx.x;
    if (idx >= COUT * KDIM) return;
    int co = idx / KDIM;
    int r  = idx - co * KDIM;     // cin*9 + khkw (source order)
    int cin  = r / 9;
    int khkw = r - cin * 9;
    int kp = khkw * CIN + cin;    // target K order
    long long w = load_val(wq, idx, g_flag);
    g_W[(size_t)co * KDIM + kp] = (int8_t)(w >> 8);                        // hi s8
    g_W[(size_t)COUT * KDIM + (size_t)co * KDIM + kp] = (int8_t)(w & 255); // lo u8
}

// ---------------- kernel 3: implicit-im2col GEMM + epilogue ----------------
__global__ void __launch_bounds__(THREADS, 1)
gemm_kernel(const void* __restrict__ bias, void* __restrict__ outv) {
    extern __shared__ char smem[];
    const uint32_t smb = smem_to_u32(smem);
    const int tid  = threadIdx.x;
    const int lane = tid & 31;
    const int wrp  = tid >> 5;
    const int wm   = wrp & 3;
    const int wn   = wrp >> 2;

    const int mt = blockIdx.x >> 1;
    const int nt = blockIdx.x & 1;

    const int row = tid >> 2;     // 0..127
    const int c16 = tid & 3;      // 16B column group (covers 0..63; +64 second half)

    const int p_ = mt * CTA_M + row;
    const int n_ = p_ / HW2;
    const int hw_ = p_ - n_ * HW2;
    const int h_ = hw_ / HW;
    const int w_ = hw_ - h_ * HW;
    // center-tap base of this pixel's padded-NHWC row (128B per pixel)
    const int8_t* Arow = g_Xt
        + ((size_t)((n_ * PHW + h_ + 1) * PHW + (w_ + 1))) * CIN;
    const int8_t* Whi = g_W + (size_t)(nt * CTA_N + row) * KDIM;
    const int8_t* Wlo = Whi + (size_t)COUT * KDIM;

    const uint32_t sRow = smb + row * PITCH + c16 * 16;

    int acch[2][4][4];
    int accl[2][4][4];
#pragma unroll
    for (int mb = 0; mb < 2; mb++)
#pragma unroll
        for (int nb = 0; nb < 4; nb++)
#pragma unroll
            for (int i = 0; i < 4; i++) { acch[mb][nb][i] = 0; accl[mb][nb][i] = 0; }

    // chunk kc = khkw (kh=kc/3, kw=kc%3); 128B contiguous per row
    auto load_chunk = [&](int kc, int buf) {
        int kh = kc / 3;
        int kw = kc - kh * 3;
        const int8_t* asrc = Arow + ((kh - 1) * PHW + (kw - 1)) * CIN + c16 * 16;
        const int8_t* hsrc = Whi + kc * KC + c16 * 16;
        const int8_t* lsrc = Wlo + kc * KC + c16 * 16;
        uint32_t sb = sRow + buf * SM_STAGE;
        cp16(sb,                     asrc);
        cp16(sb + 64,                asrc + 64);
        cp16(sb + SM_TILE,           hsrc);
        cp16(sb + SM_TILE + 64,      hsrc + 64);
        cp16(sb + 2 * SM_TILE,       lsrc);
        cp16(sb + 2 * SM_TILE + 64,  lsrc + 64);
    };

    // prologue: fill STAGES-1 stages
#pragma unroll
    for (int s = 0; s < STAGES - 1; s++) { load_chunk(s, s); CP_COMMIT(); }

    int buf = 0;
    for (int kc = 0; kc < NCHUNK; kc++) {
        CP_WAIT(STAGES - 2);
        __syncthreads();                       // single barrier per chunk
        {
            int nk = kc + STAGES - 1;
            int nbuf = buf + STAGES - 1; if (nbuf >= STAGES) nbuf -= STAGES;
            if (nk < NCHUNK) load_chunk(nk, nbuf);
            CP_COMMIT();
        }

        const uint32_t smA  = smb + buf * SM_STAGE;
        const uint32_t smBh = smA + SM_TILE;
        const uint32_t smBl = smA + 2 * SM_TILE;

#pragma unroll
        for (int ks = 0; ks < 4; ks++) {       // 4 x k32 per 128-chunk
            uint32_t a[2][4];
#pragma unroll
            for (int mb = 0; mb < 2; mb++) {
                uint32_t addr = smA + (uint32_t)((wm * 32 + mb * 16 + (lane & 15)) * PITCH
                                                 + (ks * 2 + (lane >> 4)) * 16);
                ldsm_x4(a[mb], addr);
            }
            uint32_t bh[2][4], bl[2][4];
#pragma unroll
            for (int nb2 = 0; nb2 < 2; nb2++) {
                uint32_t boff = (uint32_t)((wn * 32 + nb2 * 16 + (lane & 7) + ((lane >> 4) << 3)) * PITCH
                                           + (ks * 2 + ((lane >> 3) & 1)) * 16);
                ldsm_x4(bh[nb2], smBh + boff);
                ldsm_x4(bl[nb2], smBl + boff);
            }
#pragma unroll
            for (int mb = 0; mb < 2; mb++)
#pragma unroll
                for (int nb2 = 0; nb2 < 2; nb2++)
#pragma unroll
                    for (int q = 0; q < 2; q++) {
                        mma_s8s8(acch[mb][nb2 * 2 + q], a[mb], &bh[nb2][q * 2]);
                        mma_s8u8(accl[mb][nb2 * 2 + q], a[mb], &bl[nb2][q * 2]);
                    }
        }
        if (++buf == STAGES) buf = 0;
    }

    // ---- epilogue: combine hi/lo in i64, bias, shift, store ----
    const int flag = g_flag;
#pragma unroll
    for (int mb = 0; mb < 2; mb++) {
#pragma unroll
        for (int nb = 0; nb < 4; nb++) {
            int p0  = mt * CTA_M + wm * 32 + mb * 16 + (lane >> 2);
            int co0 = nt * CTA_N + wn * 32 + nb * 8 + (lane & 3) * 2;
#pragma unroll
            for (int i = 0; i < 4; i++) {
                int p  = p0 + ((i >= 2) ? 8 : 0);
                int co = co0 + (i & 1);
                long long b = load_val(bias, co, flag);
                long long v = (((long long)acch[mb][nb][i] << 8)
                               + (long long)accl[mb][nb][i] + b) >> SHIFT;
                int n  = p / HW2;
                int hw = p - n * HW2;
                size_t oi = ((size_t)(n * COUT + co)) * HW2 + hw;
                if (flag == FLAG_I64)      ((long long*)outv)[oi] = v;
                else if (flag == FLAG_F64) ((double*)outv)[oi] = (double)v;
                else                       ((float*)outv)[oi] = (float)v;
            }
        }
    }
}

// ---------------- launch ----------------
extern "C" void kernel_launch(void* const* d_in, const int* in_sizes, int n_in,
                              void* d_out, int out_size) {
    const void* x = nullptr; const void* wq = nullptr; const void* bias = nullptr;
    for (int i = 0; i < n_in; i++) {
        if (in_sizes[i] == NB * CIN * HW2)      x    = d_in[i];
        else if (in_sizes[i] == COUT * KDIM)    wq   = d_in[i];
        else if (in_sizes[i] == COUT)           bias = d_in[i];
    }
    (void)out_size;

    detect_kernel<<<1, 32>>>(x);
    transpose_kernel<<<NB * PHW, 256>>>(x);
    prepw_kernel<<<(COUT * KDIM + 255) / 256, 256>>>(wq);

    cudaFuncSetAttribute(gemm_kernel, cudaFuncAttributeMaxDynamicSharedMemorySize, SM_TOTAL);
    gemm_kernel<<<M_TILES * N_TILES, THREADS, SM_TOTAL>>>(bias, d_out);
}

// round 9
// speedup vs baseline: 1.0361x; 1.0361x over previous
#include <cuda_runtime.h>
#include <cuda.h>
#include <cstdint>

// ============================================================
// QuantizedConv2d exact int conv via split-weight int8 mma.sync GEMM
//   x[8,128,56,56], w[256,128,3,3], bias[256], shift=16 (structural)
//   out[8,256,56,56] = (conv(x,w)+bias) >> 16
// w = (w>>8)*256 + (w&255): hi s8 / lo u8 planes; two s32 GEMMs, i64 combine.
// NHWC repack + zero halo + implicit im2col (K = (kh,kw,cin)).
// R8 evidence: tensor BUSY TIME is invariant (~26.5us); rest is exposed
// latency, and occ=25% (1 CTA/SM) means barriers stall the whole SM.
// This round: CTA 128x64, 256 threads -> 32K regs/CTA -> 2 CTAs/SM (occ 50%),
// cross-CTA latency hiding. KC=64/PITCH=80/4-stage (best-known) mainloop.
// ============================================================

static constexpr int NB    = 8;
static constexpr int CIN   = 128;
static constexpr int COUT  = 256;
static constexpr int HW    = 56;
static constexpr int HW2   = HW * HW;           // 3136
static constexpr int NPIX  = NB * HW2;          // 25088
static constexpr int KDIM  = CIN * 9;           // 1152
static constexpr int SHIFT = 16;
static constexpr int PHW   = HW + 2;            // 58

static constexpr int CTA_M = 128;               // pixels
static constexpr int CTA_N = 64;                // couts
static constexpr int KC    = 64;
static constexpr int NCHUNK = KDIM / KC;        // 18
static constexpr int M_TILES = NPIX / CTA_M;    // 196
static constexpr int N_TILES = COUT / CTA_N;    // 4
static constexpr int THREADS = 256;             // 8 warps: 4(M) x 2(N)

static constexpr int STAGES  = 4;
static constexpr int PITCH   = 80;
static constexpr int SM_TILE_A = 128 * PITCH;   // 10240
static constexpr int SM_TILE_B = 64 * PITCH;    // 5120
static constexpr int SM_STAGE  = SM_TILE_A + 2 * SM_TILE_B;  // 20480
static constexpr int SM_TOTAL  = STAGES * SM_STAGE;          // 81920

static constexpr int FLAG_I64 = 0, FLAG_I32 = 1, FLAG_F32 = 2, FLAG_F64 = 3;

// ---------------- scratch ----------------
__device__ __align__(128) int8_t g_Xt[(size_t)NB * PHW * PHW * CIN];  // 3.44MB
__device__ __align__(128) int8_t g_W[2 * (size_t)COUT * KDIM];        // hi|lo planes
__device__ int g_flag;

// ---------------- PTX helpers ----------------
__device__ __forceinline__ uint32_t smem_to_u32(const void* p) {
    uint32_t a;
    asm("{ .reg .u64 t; cvta.to.shared.u64 t, %1; cvt.u32.u64 %0, t; }" : "=r"(a) : "l"(p));
    return a;
}
__device__ __forceinline__ void cp16(uint32_t dst, const void* src) {
    asm volatile("cp.async.cg.shared.global [%0], [%1], 16;" :: "r"(dst), "l"(src));
}
#define CP_COMMIT() asm volatile("cp.async.commit_group;" ::: "memory")
#define CP_WAIT(n)  asm volatile("cp.async.wait_group %0;" :: "n"(n) : "memory")

__device__ __forceinline__ void ldsm_x4(uint32_t* r, uint32_t addr) {
    asm volatile("ldmatrix.sync.aligned.m8n8.x4.shared.b16 {%0,%1,%2,%3}, [%4];"
                 : "=r"(r[0]), "=r"(r[1]), "=r"(r[2]), "=r"(r[3]) : "r"(addr));
}
__device__ __forceinline__ void mma_s8s8(int* c, const uint32_t* a, const uint32_t* b) {
    asm volatile("mma.sync.aligned.m16n8k32.row.col.s32.s8.s8.s32 "
                 "{%0,%1,%2,%3}, {%4,%5,%6,%7}, {%8,%9}, {%0,%1,%2,%3};"
                 : "+r"(c[0]), "+r"(c[1]), "+r"(c[2]), "+r"(c[3])
                 : "r"(a[0]), "r"(a[1]), "r"(a[2]), "r"(a[3]), "r"(b[0]), "r"(b[1]));
}
__device__ __forceinline__ void mma_s8u8(int* c, const uint32_t* a, const uint32_t* b) {
    asm volatile("mma.sync.aligned.m16n8k32.row.col.s32.s8.u8.s32 "
                 "{%0,%1,%2,%3}, {%4,%5,%6,%7}, {%8,%9}, {%0,%1,%2,%3};"
                 : "+r"(c[0]), "+r"(c[1]), "+r"(c[2]), "+r"(c[3])
                 : "r"(a[0]), "r"(a[1]), "r"(a[2]), "r"(a[3]), "r"(b[0]), "r"(b[1]));
}

// ---------------- dtype detection (warp-parallel) ----------------
__global__ void detect_kernel(const void* xraw) {
    if (blockIdx.x != 0) return;
    int lane = threadIdx.x & 31;
    const int* w = (const int*)xraw;
    int signext = 0, small = 0, lozero = 0;
#pragma unroll
    for (int j = 0; j < 4; j++) {
        int i = lane + j * 32;
        int lo = w[2 * i], hi = w[2 * i + 1];
        if (hi == (lo < 0 ? -1 : 0)) signext++;
        if (lo >= -256 && lo < 256 && hi >= -256 && hi < 256) small++;
        if (lo == 0) lozero++;
    }
#pragma unroll
    for (int off = 16; off > 0; off >>= 1) {
        signext += __shfl_down_sync(0xffffffffu, signext, off);
        small   += __shfl_down_sync(0xffffffffu, small,   off);
        lozero  += __shfl_down_sync(0xffffffffu, lozero,  off);
    }
    if (lane == 0) {
        int f;
        if (signext >= 120)      f = FLAG_I64;
        else if (small >= 120)   f = FLAG_I32;
        else if (lozero >= 100)  f = FLAG_F64;
        else                     f = FLAG_F32;
        g_flag = f;
    }
}

__device__ __forceinline__ long long load_val(const void* p, size_t idx, int flag) {
    if (flag == FLAG_I64) return ((const long long*)p)[idx];
    if (flag == FLAG_I32) return (long long)((const int*)p)[idx];
    if (flag == FLAG_F64) return __double2ll_rn(((const double*)p)[idx]);
    return (long long)__float2ll_rn(((const float*)p)[idx]);
}

// ---------------- kernel 1: pack + NCHW->NHWC transpose with halo ----------------
__global__ void __launch_bounds__(256)
transpose_kernel(const void* __restrict__ x) {
    __shared__ int8_t s[CIN * (HW + 1)];
    int b  = blockIdx.x;
    int n  = b / PHW;
    int ph = b - n * PHW;
    int8_t* dst = g_Xt + ((size_t)(n * PHW + ph) * PHW) * CIN;
    int t = threadIdx.x;

    if (ph == 0 || ph == PHW - 1) {
        for (int i = t; i < PHW * CIN / 4; i += 256) ((int*)dst)[i] = 0;
        return;
    }
    int h = ph - 1;
    const int flag = g_flag;
    for (int i = t; i < CIN * HW; i += 256) {
        int c = i / HW, w = i - c * HW;
        long long v = load_val(x, ((size_t)(n * CIN + c) * HW + h) * HW + w, flag);
        s[c * (HW + 1) + w] = (int8_t)v;
    }
    __syncthreads();
    for (int i = t; i < PHW * (CIN / 4); i += 256) {
        int pw = i >> 5;
        int c0 = (i & 31) * 4;
        uint32_t word = 0;
        if (pw >= 1 && pw <= HW) {
            int w = pw - 1;
            uchar4 u;
            u.x = (uint8_t)s[(c0 + 0) * (HW + 1) + w];
            u.y = (uint8_t)s[(c0 + 1) * (HW + 1) + w];
            u.z = (uint8_t)s[(c0 + 2) * (HW + 1) + w];
            u.w = (uint8_t)s[(c0 + 3) * (HW + 1) + w];
            word = *(uint32_t*)&u;
        }
        ((uint32_t*)dst)[i] = word;
    }
}

// ---------------- kernel 2: weight planes, K reordered to (khkw, cin) ----------------
__global__ void prepw_kernel(const void* __restrict__ wq) {
    int idx = blockIdx.x * blockDim.x + threadIdx.x;
    if (idx >= COUT * KDIM) return;
    int co = idx / KDIM;
    int r  = idx - co * KDIM;
    int cin  = r / 9;
    int khkw = r - cin * 9;
    int kp = khkw * CIN + cin;
    long long w = load_val(wq, idx, g_flag);
    g_W[(size_t)co * KDIM + kp] = (int8_t)(w >> 8);
    g_W[(size_t)COUT * KDIM + (size_t)co * KDIM + kp] = (int8_t)(w & 255);
}

// ---------------- kernel 3: implicit-im2col GEMM + epilogue ----------------
__global__ void __launch_bounds__(THREADS, 2)
gemm_kernel(const void* __restrict__ bias, void* __restrict__ outv) {
    extern __shared__ char smem[];
    const uint32_t smb = smem_to_u32(smem);
    const int tid  = threadIdx.x;
    const int lane = tid & 31;
    const int wrp  = tid >> 5;     // 0..7
    const int wm   = wrp & 3;      // warp M index
    const int wn   = wrp >> 2;     // warp N index (0..1)

    const int mt = blockIdx.x >> 2;   // 0..195
    const int nt = blockIdx.x & 3;    // 0..3

    // load assignments: A has 512 slots (2 per thread), B 256 slots (1 each)
    const int rowA0 = tid >> 2;           // 0..63
    const int rowA1 = rowA0 + 64;         // 64..127
    const int c16   = tid & 3;
    const int rowB  = tid >> 2;           // 0..63

    auto arow_ptr = [&](int r) -> const int8_t* {
        int p_ = mt * CTA_M + r;
        int n_ = p_ / HW2;
        int hw_ = p_ - n_ * HW2;
        int h_ = hw_ / HW;
        int w_ = hw_ - h_ * HW;
        return g_Xt + ((size_t)((n_ * PHW + h_ + 1) * PHW + (w_ + 1))) * CIN + c16 * 16;
    };
    const int8_t* Arow0 = arow_ptr(rowA0);
    const int8_t* Arow1 = arow_ptr(rowA1);
    const int8_t* Whi = g_W + (size_t)(nt * CTA_N + rowB) * KDIM + c16 * 16;
    const int8_t* Wlo = Whi + (size_t)COUT * KDIM;

    const uint32_t sA0 = smb + rowA0 * PITCH + c16 * 16;
    const uint32_t sA1 = smb + rowA1 * PITCH + c16 * 16;
    const uint32_t sB  = smb + SM_TILE_A + rowB * PITCH + c16 * 16;

    int acch[2][4][4];
    int accl[2][4][4];
#pragma unroll
    for (int mb = 0; mb < 2; mb++)
#pragma unroll
        for (int nb = 0; nb < 4; nb++)
#pragma unroll
            for (int i = 0; i < 4; i++) { acch[mb][nb][i] = 0; accl[mb][nb][i] = 0; }

    auto load_chunk = [&](int kc, int buf) {
        int khkw = kc >> 1;
        int kh = khkw / 3;
        int kw = khkw - kh * 3;
        int off = ((kh - 1) * PHW + (kw - 1)) * CIN + (kc & 1) * KC;
        uint32_t sb = buf * SM_STAGE;
        cp16(sA0 + sb, Arow0 + off);
        cp16(sA1 + sb, Arow1 + off);
        cp16(sB + sb,               Whi + kc * KC);
        cp16(sB + sb + SM_TILE_B,   Wlo + kc * KC);
    };

#pragma unroll
    for (int s = 0; s < STAGES - 1; s++) { load_chunk(s, s); CP_COMMIT(); }

    for (int kc = 0; kc < NCHUNK; kc++) {
        CP_WAIT(STAGES - 2);
        __syncthreads();
        {
            int nk = kc + STAGES - 1;
            if (nk < NCHUNK) load_chunk(nk, nk & (STAGES - 1));
            CP_COMMIT();
        }

        const uint32_t smA  = smb + (kc & (STAGES - 1)) * SM_STAGE;
        const uint32_t smBh = smA + SM_TILE_A;
        const uint32_t smBl = smBh + SM_TILE_B;

#pragma unroll
        for (int ks = 0; ks < 2; ks++) {
            uint32_t a[2][4];
#pragma unroll
            for (int mb = 0; mb < 2; mb++) {
                uint32_t addr = smA + (uint32_t)((wm * 32 + mb * 16 + (lane & 15)) * PITCH
                                                 + (ks * 2 + (lane >> 4)) * 16);
                ldsm_x4(a[mb], addr);
            }
            uint32_t bh[2][4], bl[2][4];
#pragma unroll
            for (int nb2 = 0; nb2 < 2; nb2++) {
                uint32_t boff = (uint32_t)((wn * 32 + nb2 * 16 + (lane & 7) + ((lane >> 4) << 3)) * PITCH
                                           + (ks * 2 + ((lane >> 3) & 1)) * 16);
                ldsm_x4(bh[nb2], smBh + boff);
                ldsm_x4(bl[nb2], smBl + boff);
            }
#pragma unroll
            for (int mb = 0; mb < 2; mb++)
#pragma unroll
                for (int nb2 = 0; nb2 < 2; nb2++)
#pragma unroll
                    for (int q = 0; q < 2; q++) {
                        mma_s8s8(acch[mb][nb2 * 2 + q], a[mb], &bh[nb2][q * 2]);
                        mma_s8u8(accl[mb][nb2 * 2 + q], a[mb], &bl[nb2][q * 2]);
                    }
        }
    }

    // ---- epilogue ----
    const int flag = g_flag;
#pragma unroll
    for (int mb = 0; mb < 2; mb++) {
#pragma unroll
        for (int nb = 0; nb < 4; nb++) {
            int p0  = mt * CTA_M + wm * 32 + mb * 16 + (lane >> 2);
            int co0 = nt * CTA_N + wn * 32 + nb * 8 + (lane & 3) * 2;
#pragma unroll
            for (int i = 0; i < 4; i++) {
                int p  = p0 + ((i >= 2) ? 8 : 0);
                int co = co0 + (i & 1);
                long long b = load_val(bias, co, flag);
                long long v = (((long long)acch[mb][nb][i] << 8)
                               + (long long)accl[mb][nb][i] + b) >> SHIFT;
                int n  = p / HW2;
                int hw = p - n * HW2;
                size_t oi = ((size_t)(n * COUT + co)) * HW2 + hw;
                if (flag == FLAG_I64)      ((long long*)outv)[oi] = v;
                else if (flag == FLAG_F64) ((double*)outv)[oi] = (double)v;
                else                       ((float*)outv)[oi] = (float)v;
            }
        }
    }
}

// ---------------- launch ----------------
extern "C" void kernel_launch(void* const* d_in, const int* in_sizes, int n_in,
                              void* d_out, int out_size) {
    const void* x = nullptr; const void* wq = nullptr; const void* bias = nullptr;
    for (int i = 0; i < n_in; i++) {
        if (in_sizes[i] == NB * CIN * HW2)      x    = d_in[i];
        else if (in_sizes[i] == COUT * KDIM)    wq   = d_in[i];
        else if (in_sizes[i] == COUT)           bias = d_in[i];
    }
    (void)out_size;

    detect_kernel<<<1, 32>>>(x);
    transpose_kernel<<<NB * PHW, 256>>>(x);
    prepw_kernel<<<(COUT * KDIM + 255) / 256, 256>>>(wq);

    cudaFuncSetAttribute(gemm_kernel, cudaFuncAttributeMaxDynamicSharedMemorySize, SM_TOTAL);
    gemm_kernel<<<M_TILES * N_TILES, THREADS, SM_TOTAL>>>(bias, d_out);
}

// round 10
// speedup vs baseline: 1.1443x; 1.1045x over previous
#include <cuda_runtime.h>
#include <cuda.h>
#include <cstdint>

// ============================================================
// QuantizedConv2d exact int conv via split-weight int8 mma.sync GEMM
//   x[8,128,56,56], w[256,128,3,3], bias[256], shift=16 (structural)
//   out[8,256,56,56] = (conv(x,w)+bias) >> 16
// w = (w>>8)*256 + (w&255): hi s8 / lo u8 planes; two s32 GEMMs, i64 combine.
// NHWC repack + zero halo + implicit im2col (K = (kh,kw,cin)).
// R9 lesson: 128 regs/thread pins the SM at 16 warps no matter the CTA shape.
// This round: warp tile 32x16 (32 accumulators), CTA 128x32, 256 threads,
// __launch_bounds__(256,3) -> 3 CTAs/SM = 24 warps. nt-fastest grid order
// keeps the 8x A-tile re-reads L2-resident.
// ============================================================

static constexpr int NB    = 8;
static constexpr int CIN   = 128;
static constexpr int COUT  = 256;
static constexpr int HW    = 56;
static constexpr int HW2   = HW * HW;           // 3136
static constexpr int NPIX  = NB * HW2;          // 25088
static constexpr int KDIM  = CIN * 9;           // 1152
static constexpr int SHIFT = 16;
static constexpr int PHW   = HW + 2;            // 58

static constexpr int CTA_M = 128;               // pixels
static constexpr int CTA_N = 32;                // couts
static constexpr int KC    = 64;
static constexpr int NCHUNK = KDIM / KC;        // 18
static constexpr int M_TILES = NPIX / CTA_M;    // 196
static constexpr int N_TILES = COUT / CTA_N;    // 8
static constexpr int THREADS = 256;             // 8 warps: 4(M) x 2(N), tile 32x16

static constexpr int STAGES  = 4;
static constexpr int PITCH   = 80;
static constexpr int SM_TILE_A = 128 * PITCH;   // 10240
static constexpr int SM_TILE_B = 32 * PITCH;    // 2560
static constexpr int SM_STAGE  = SM_TILE_A + 2 * SM_TILE_B;  // 15360
static constexpr int SM_TOTAL  = STAGES * SM_STAGE;          // 61440

static constexpr int FLAG_I64 = 0, FLAG_I32 = 1, FLAG_F32 = 2, FLAG_F64 = 3;

// ---------------- scratch ----------------
__device__ __align__(128) int8_t g_Xt[(size_t)NB * PHW * PHW * CIN];  // 3.44MB
__device__ __align__(128) int8_t g_W[2 * (size_t)COUT * KDIM];        // hi|lo planes
__device__ int g_flag;

// ---------------- PTX helpers ----------------
__device__ __forceinline__ uint32_t smem_to_u32(const void* p) {
    uint32_t a;
    asm("{ .reg .u64 t; cvta.to.shared.u64 t, %1; cvt.u32.u64 %0, t; }" : "=r"(a) : "l"(p));
    return a;
}
__device__ __forceinline__ void cp16(uint32_t dst, const void* src) {
    asm volatile("cp.async.cg.shared.global [%0], [%1], 16;" :: "r"(dst), "l"(src));
}
#define CP_COMMIT() asm volatile("cp.async.commit_group;" ::: "memory")
#define CP_WAIT(n)  asm volatile("cp.async.wait_group %0;" :: "n"(n) : "memory")

__device__ __forceinline__ void ldsm_x4(uint32_t* r, uint32_t addr) {
    asm volatile("ldmatrix.sync.aligned.m8n8.x4.shared.b16 {%0,%1,%2,%3}, [%4];"
                 : "=r"(r[0]), "=r"(r[1]), "=r"(r[2]), "=r"(r[3]) : "r"(addr));
}
__device__ __forceinline__ void mma_s8s8(int* c, const uint32_t* a, const uint32_t* b) {
    asm volatile("mma.sync.aligned.m16n8k32.row.col.s32.s8.s8.s32 "
                 "{%0,%1,%2,%3}, {%4,%5,%6,%7}, {%8,%9}, {%0,%1,%2,%3};"
                 : "+r"(c[0]), "+r"(c[1]), "+r"(c[2]), "+r"(c[3])
                 : "r"(a[0]), "r"(a[1]), "r"(a[2]), "r"(a[3]), "r"(b[0]), "r"(b[1]));
}
__device__ __forceinline__ void mma_s8u8(int* c, const uint32_t* a, const uint32_t* b) {
    asm volatile("mma.sync.aligned.m16n8k32.row.col.s32.s8.u8.s32 "
                 "{%0,%1,%2,%3}, {%4,%5,%6,%7}, {%8,%9}, {%0,%1,%2,%3};"
                 : "+r"(c[0]), "+r"(c[1]), "+r"(c[2]), "+r"(c[3])
                 : "r"(a[0]), "r"(a[1]), "r"(a[2]), "r"(a[3]), "r"(b[0]), "r"(b[1]));
}

// ---------------- dtype detection (warp-parallel) ----------------
__global__ void detect_kernel(const void* xraw) {
    if (blockIdx.x != 0) return;
    int lane = threadIdx.x & 31;
    const int* w = (const int*)xraw;
    int signext = 0, small = 0, lozero = 0;
#pragma unroll
    for (int j = 0; j < 4; j++) {
        int i = lane + j * 32;
        int lo = w[2 * i], hi = w[2 * i + 1];
        if (hi == (lo < 0 ? -1 : 0)) signext++;
        if (lo >= -256 && lo < 256 && hi >= -256 && hi < 256) small++;
        if (lo == 0) lozero++;
    }
#pragma unroll
    for (int off = 16; off > 0; off >>= 1) {
        signext += __shfl_down_sync(0xffffffffu, signext, off);
        small   += __shfl_down_sync(0xffffffffu, small,   off);
        lozero  += __shfl_down_sync(0xffffffffu, lozero,  off);
    }
    if (lane == 0) {
        int f;
        if (signext >= 120)      f = FLAG_I64;
        else if (small >= 120)   f = FLAG_I32;
        else if (lozero >= 100)  f = FLAG_F64;
        else                     f = FLAG_F32;
        g_flag = f;
    }
}

__device__ __forceinline__ long long load_val(const void* p, size_t idx, int flag) {
    if (flag == FLAG_I64) return ((const long long*)p)[idx];
    if (flag == FLAG_I32) return (long long)((const int*)p)[idx];
    if (flag == FLAG_F64) return __double2ll_rn(((const double*)p)[idx]);
    return (long long)__float2ll_rn(((const float*)p)[idx]);
}

// ---------------- kernel 1: pack + NCHW->NHWC transpose with halo ----------------
__global__ void __launch_bounds__(256)
transpose_kernel(const void* __restrict__ x) {
    __shared__ int8_t s[CIN * (HW + 1)];
    int b  = blockIdx.x;
    int n  = b / PHW;
    int ph = b - n * PHW;
    int8_t* dst = g_Xt + ((size_t)(n * PHW + ph) * PHW) * CIN;
    int t = threadIdx.x;

    if (ph == 0 || ph == PHW - 1) {
        for (int i = t; i < PHW * CIN / 4; i += 256) ((int*)dst)[i] = 0;
        return;
    }
    int h = ph - 1;
    const int flag = g_flag;
    for (int i = t; i < CIN * HW; i += 256) {
        int c = i / HW, w = i - c * HW;
        long long v = load_val(x, ((size_t)(n * CIN + c) * HW + h) * HW + w, flag);
        s[c * (HW + 1) + w] = (int8_t)v;
    }
    __syncthreads();
    for (int i = t; i < PHW * (CIN / 4); i += 256) {
        int pw = i >> 5;
        int c0 = (i & 31) * 4;
        uint32_t word = 0;
        if (pw >= 1 && pw <= HW) {
            int w = pw - 1;
            uchar4 u;
            u.x = (uint8_t)s[(c0 + 0) * (HW + 1) + w];
            u.y = (uint8_t)s[(c0 + 1) * (HW + 1) + w];
            u.z = (uint8_t)s[(c0 + 2) * (HW + 1) + w];
            u.w = (uint8_t)s[(c0 + 3) * (HW + 1) + w];
            word = *(uint32_t*)&u;
        }
        ((uint32_t*)dst)[i] = word;
    }
}

// ---------------- kernel 2: weight planes, K reordered to (khkw, cin) ----------------
__global__ void prepw_kernel(const void* __restrict__ wq) {
    int idx = blockIdx.x * blockDim.x + threadIdx.x;
    if (idx >= COUT * KDIM) return;
    int co = idx / KDIM;
    int r  = idx - co * KDIM;
    int cin  = r / 9;
    int khkw = r - cin * 9;
    int kp = khkw * CIN + cin;
    long long w = load_val(wq, idx, g_flag);
    g_W[(size_t)co * KDIM + kp] = (int8_t)(w >> 8);
    g_W[(size_t)COUT * KDIM + (size_t)co * KDIM + kp] = (int8_t)(w & 255);
}

// ---------------- kernel 3: implicit-im2col GEMM + epilogue ----------------
__global__ void __launch_bounds__(THREADS, 3)
gemm_kernel(const void* __restrict__ bias, void* __restrict__ outv) {
    extern __shared__ char smem[];
    const uint32_t smb = smem_to_u32(smem);
    const int tid  = threadIdx.x;
    const int lane = tid & 31;
    const int wrp  = tid >> 5;     // 0..7
    const int wm   = wrp & 3;      // warp M index (0..3), tile 32 rows
    const int wn   = wrp >> 2;     // warp N index (0..1), tile 16 cols

    const int mt = blockIdx.x >> 3;   // 0..195
    const int nt = blockIdx.x & 7;    // 0..7

    // A loads: 512 slots (2/thread). B loads: 256 slots (1/thread).
    const int rowA0 = tid >> 2;           // 0..63
    const int rowA1 = rowA0 + 64;
    const int c16   = tid & 3;
    const int planeB = tid >> 7;          // 0..1 (hi/lo)
    const int rowB   = (tid >> 2) & 31;   // 0..31

    auto arow_ptr = [&](int r) -> const int8_t* {
        int p_ = mt * CTA_M + r;
        int n_ = p_ / HW2;
        int hw_ = p_ - n_ * HW2;
        int h_ = hw_ / HW;
        int w_ = hw_ - h_ * HW;
        return g_Xt + ((size_t)((n_ * PHW + h_ + 1) * PHW + (w_ + 1))) * CIN + c16 * 16;
    };
    const int8_t* Arow0 = arow_ptr(rowA0);
    const int8_t* Arow1 = arow_ptr(rowA1);
    const int8_t* Wb = g_W + (size_t)planeB * COUT * KDIM
                       + (size_t)(nt * CTA_N + rowB) * KDIM + c16 * 16;

    const uint32_t sA0 = smb + rowA0 * PITCH + c16 * 16;
    const uint32_t sA1 = smb + rowA1 * PITCH + c16 * 16;
    const uint32_t sBw = smb + SM_TILE_A + planeB * SM_TILE_B + rowB * PITCH + c16 * 16;

    int acch[2][2][4];
    int accl[2][2][4];
#pragma unroll
    for (int mb = 0; mb < 2; mb++)
#pragma unroll
        for (int q = 0; q < 2; q++)
#pragma unroll
            for (int i = 0; i < 4; i++) { acch[mb][q][i] = 0; accl[mb][q][i] = 0; }

    auto load_chunk = [&](int kc, int buf) {
        int khkw = kc >> 1;
        int kh = khkw / 3;
        int kw = khkw - kh * 3;
        int off = ((kh - 1) * PHW + (kw - 1)) * CIN + (kc & 1) * KC;
        uint32_t sb = buf * SM_STAGE;
        cp16(sA0 + sb, Arow0 + off);
        cp16(sA1 + sb, Arow1 + off);
        cp16(sBw + sb, Wb + kc * KC);
    };

#pragma unroll
    for (int s = 0; s < STAGES - 1; s++) { load_chunk(s, s); CP_COMMIT(); }

    for (int kc = 0; kc < NCHUNK; kc++) {
        CP_WAIT(STAGES - 2);
        __syncthreads();
        {
            int nk = kc + STAGES - 1;
            if (nk < NCHUNK) load_chunk(nk, nk & (STAGES - 1));
            CP_COMMIT();
        }

        const uint32_t smA  = smb + (kc & (STAGES - 1)) * SM_STAGE;
        const uint32_t smBh = smA + SM_TILE_A;
        const uint32_t smBl = smBh + SM_TILE_B;

#pragma unroll
        for (int ks = 0; ks < 2; ks++) {
            uint32_t a[2][4];
#pragma unroll
            for (int mb = 0; mb < 2; mb++) {
                uint32_t addr = smA + (uint32_t)((wm * 32 + mb * 16 + (lane & 15)) * PITCH
                                                 + (ks * 2 + (lane >> 4)) * 16);
                ldsm_x4(a[mb], addr);
            }
            // B fragments: one 16-row block per warp (rows wn*16..wn*16+15), both planes
            uint32_t bh[4], bl[4];
            {
                uint32_t boff = (uint32_t)((wn * 16 + (lane & 7) + ((lane >> 4) << 3)) * PITCH
                                           + (ks * 2 + ((lane >> 3) & 1)) * 16);
                ldsm_x4(bh, smBh + boff);
                ldsm_x4(bl, smBl + boff);
            }
#pragma unroll
            for (int mb = 0; mb < 2; mb++)
#pragma unroll
                for (int q = 0; q < 2; q++) {
                    mma_s8s8(acch[mb][q], a[mb], &bh[q * 2]);
                    mma_s8u8(accl[mb][q], a[mb], &bl[q * 2]);
                }
        }
    }

    // ---- epilogue ----
    const int flag = g_flag;
#pragma unroll
    for (int mb = 0; mb < 2; mb++) {
#pragma unroll
        for (int q = 0; q < 2; q++) {
            int p0  = mt * CTA_M + wm * 32 + mb * 16 + (lane >> 2);
            int co0 = nt * CTA_N + wn * 16 + q * 8 + (lane & 3) * 2;
#pragma unroll
            for (int i = 0; i < 4; i++) {
                int p  = p0 + ((i >= 2) ? 8 : 0);
                int co = co0 + (i & 1);
                long long b = load_val(bias, co, flag);
                long long v = (((long long)acch[mb][q][i] << 8)
                               + (long long)accl[mb][q][i] + b) >> SHIFT;
                int n  = p / HW2;
                int hw = p - n * HW2;
                size_t oi = ((size_t)(n * COUT + co)) * HW2 + hw;
                if (flag == FLAG_I64)      ((long long*)outv)[oi] = v;
                else if (flag == FLAG_F64) ((double*)outv)[oi] = (double)v;
                else                       ((float*)outv)[oi] = (float)v;
            }
        }
    }
}

// ---------------- launch ----------------
extern "C" void kernel_launch(void* const* d_in, const int* in_sizes, int n_in,
                              void* d_out, int out_size) {
    const void* x = nullptr; const void* wq = nullptr; const void* bias = nullptr;
    for (int i = 0; i < n_in; i++) {
        if (in_sizes[i] == NB * CIN * HW2)      x    = d_in[i];
        else if (in_sizes[i] == COUT * KDIM)    wq   = d_in[i];
        else if (in_sizes[i] == COUT)           bias = d_in[i];
    }
    (void)out_size;

    detect_kernel<<<1, 32>>>(x);
    transpose_kernel<<<NB * PHW, 256>>>(x);
    prepw_kernel<<<(COUT * KDIM + 255) / 256, 256>>>(wq);

    cudaFuncSetAttribute(gemm_kernel, cudaFuncAttributeMaxDynamicSharedMemorySize, SM_TOTAL);
    gemm_kernel<<<M_TILES * N_TILES, THREADS, SM_TOTAL>>>(bias, d_out);
}

// round 11
// speedup vs baseline: 1.2153x; 1.0621x over previous
#include <cuda_runtime.h>
#include <cuda.h>
#include <cstdint>

// ============================================================
// QuantizedConv2d exact int conv via split-weight int8 mma.sync GEMM
//   x[8,128,56,56], w[256,128,3,3], bias[256], shift=16 (structural)
//   out[8,256,56,56] = (conv(x,w)+bias) >> 16
// w = (w>>8)*256 + (w&255): hi s8 / lo u8 planes; two s32 GEMMs, i64 combine.
// NHWC repack + zero halo + implicit im2col (K = (kh,kw,cin)).
// R10 evidence: GEMM plateau ~62us is co-limited (L1 56%, tensor 43%) and
// grid 1568 @ 3 CTA/SM = 3.53 waves wastes a fractional wave. This round:
// PERSISTENT GEMM (grid 444 = 1 wave, tile loop, one barrier between tiles)
// + merged prep kernel. Mainloop itself unchanged from R10 (regs<=80 kept).
// ============================================================

static constexpr int NB    = 8;
static constexpr int CIN   = 128;
static constexpr int COUT  = 256;
static constexpr int HW    = 56;
static constexpr int HW2   = HW * HW;           // 3136
static constexpr int NPIX  = NB * HW2;          // 25088
static constexpr int KDIM  = CIN * 9;           // 1152
static constexpr int SHIFT = 16;
static constexpr int PHW   = HW + 2;            // 58

static constexpr int CTA_M = 128;
static constexpr int CTA_N = 32;
static constexpr int KC    = 64;
static constexpr int NCHUNK = KDIM / KC;        // 18
static constexpr int M_TILES = NPIX / CTA_M;    // 196
static constexpr int N_TILES = COUT / CTA_N;    // 8
static constexpr int NTILE_TOT = M_TILES * N_TILES;  // 1568
static constexpr int THREADS = 256;             // 8 warps: 4(M) x 2(N), tile 32x16
static constexpr int GRIDP   = 444;             // 148 SMs x 3 CTAs = one wave

static constexpr int STAGES  = 4;
static constexpr int PITCH   = 80;
static constexpr int SM_TILE_A = 128 * PITCH;   // 10240
static constexpr int SM_TILE_B = 32 * PITCH;    // 2560
static constexpr int SM_STAGE  = SM_TILE_A + 2 * SM_TILE_B;  // 15360
static constexpr int SM_TOTAL  = STAGES * SM_STAGE;          // 61440

static constexpr int FLAG_I64 = 0, FLAG_I32 = 1, FLAG_F32 = 2, FLAG_F64 = 3;

// ---------------- scratch ----------------
__device__ __align__(128) int8_t g_Xt[(size_t)NB * PHW * PHW * CIN];  // 3.44MB
__device__ __align__(128) int8_t g_W[2 * (size_t)COUT * KDIM];        // hi|lo planes
__device__ int g_flag;

// ---------------- PTX helpers ----------------
__device__ __forceinline__ uint32_t smem_to_u32(const void* p) {
    uint32_t a;
    asm("{ .reg .u64 t; cvta.to.shared.u64 t, %1; cvt.u32.u64 %0, t; }" : "=r"(a) : "l"(p));
    return a;
}
__device__ __forceinline__ void cp16(uint32_t dst, const void* src) {
    asm volatile("cp.async.cg.shared.global [%0], [%1], 16;" :: "r"(dst), "l"(src));
}
#define CP_COMMIT() asm volatile("cp.async.commit_group;" ::: "memory")
#define CP_WAIT(n)  asm volatile("cp.async.wait_group %0;" :: "n"(n) : "memory")

__device__ __forceinline__ void ldsm_x4(uint32_t* r, uint32_t addr) {
    asm volatile("ldmatrix.sync.aligned.m8n8.x4.shared.b16 {%0,%1,%2,%3}, [%4];"
                 : "=r"(r[0]), "=r"(r[1]), "=r"(r[2]), "=r"(r[3]) : "r"(addr));
}
__device__ __forceinline__ void mma_s8s8(int* c, const uint32_t* a, const uint32_t* b) {
    asm volatile("mma.sync.aligned.m16n8k32.row.col.s32.s8.s8.s32 "
                 "{%0,%1,%2,%3}, {%4,%5,%6,%7}, {%8,%9}, {%0,%1,%2,%3};"
                 : "+r"(c[0]), "+r"(c[1]), "+r"(c[2]), "+r"(c[3])
                 : "r"(a[0]), "r"(a[1]), "r"(a[2]), "r"(a[3]), "r"(b[0]), "r"(b[1]));
}
__device__ __forceinline__ void mma_s8u8(int* c, const uint32_t* a, const uint32_t* b) {
    asm volatile("mma.sync.aligned.m16n8k32.row.col.s32.s8.u8.s32 "
                 "{%0,%1,%2,%3}, {%4,%5,%6,%7}, {%8,%9}, {%0,%1,%2,%3};"
                 : "+r"(c[0]), "+r"(c[1]), "+r"(c[2]), "+r"(c[3])
                 : "r"(a[0]), "r"(a[1]), "r"(a[2]), "r"(a[3]), "r"(b[0]), "r"(b[1]));
}

// ---------------- dtype detection (warp-parallel) ----------------
__global__ void detect_kernel(const void* xraw) {
    if (blockIdx.x != 0) return;
    int lane = threadIdx.x & 31;
    const int* w = (const int*)xraw;
    int signext = 0, small = 0, lozero = 0;
#pragma unroll
    for (int j = 0; j < 4; j++) {
        int i = lane + j * 32;
        int lo = w[2 * i], hi = w[2 * i + 1];
        if (hi == (lo < 0 ? -1 : 0)) signext++;
        if (lo >= -256 && lo < 256 && hi >= -256 && hi < 256) small++;
        if (lo == 0) lozero++;
    }
#pragma unroll
    for (int off = 16; off > 0; off >>= 1) {
        signext += __shfl_down_sync(0xffffffffu, signext, off);
        small   += __shfl_down_sync(0xffffffffu, small,   off);
        lozero  += __shfl_down_sync(0xffffffffu, lozero,  off);
    }
    if (lane == 0) {
        int f;
        if (signext >= 120)      f = FLAG_I64;
        else if (small >= 120)   f = FLAG_I32;
        else if (lozero >= 100)  f = FLAG_F64;
        else                     f = FLAG_F32;
        g_flag = f;
    }
}

__device__ __forceinline__ long long load_val(const void* p, size_t idx, int flag) {
    if (flag == FLAG_I64) return ((const long long*)p)[idx];
    if (flag == FLAG_I32) return (long long)((const int*)p)[idx];
    if (flag == FLAG_F64) return __double2ll_rn(((const double*)p)[idx]);
    return (long long)__float2ll_rn(((const float*)p)[idx]);
}

// ---------------- merged prep: transpose (blocks 0..463) + weights (rest) ----------------
static constexpr int TR_BLOCKS = NB * PHW;                 // 464
static constexpr int PW_BLOCKS = (COUT * KDIM) / 256;      // 1152

__global__ void __launch_bounds__(256)
prep_kernel(const void* __restrict__ x, const void* __restrict__ wq) {
    const int flag = g_flag;
    if (blockIdx.x >= TR_BLOCKS) {
        // ---- weight planes, K reordered to (khkw, cin) ----
        int idx = (blockIdx.x - TR_BLOCKS) * 256 + threadIdx.x;
        int co = idx / KDIM;
        int r  = idx - co * KDIM;
        int cin  = r / 9;
        int khkw = r - cin * 9;
        int kp = khkw * CIN + cin;
        long long w = load_val(wq, idx, flag);
        g_W[(size_t)co * KDIM + kp] = (int8_t)(w >> 8);
        g_W[(size_t)COUT * KDIM + (size_t)co * KDIM + kp] = (int8_t)(w & 255);
        return;
    }
    // ---- pack + NCHW->NHWC transpose with halo ----
    __shared__ int8_t s[CIN * (HW + 1)];
    int b  = blockIdx.x;
    int n  = b / PHW;
    int ph = b - n * PHW;
    int8_t* dst = g_Xt + ((size_t)(n * PHW + ph) * PHW) * CIN;
    int t = threadIdx.x;

    if (ph == 0 || ph == PHW - 1) {
        for (int i = t; i < PHW * CIN / 4; i += 256) ((int*)dst)[i] = 0;
        return;
    }
    int h = ph - 1;
    for (int i = t; i < CIN * HW; i += 256) {
        int c = i / HW, w = i - c * HW;
        long long v = load_val(x, ((size_t)(n * CIN + c) * HW + h) * HW + w, flag);
        s[c * (HW + 1) + w] = (int8_t)v;
    }
    __syncthreads();
    for (int i = t; i < PHW * (CIN / 4); i += 256) {
        int pw = i >> 5;
        int c0 = (i & 31) * 4;
        uint32_t word = 0;
        if (pw >= 1 && pw <= HW) {
            int w = pw - 1;
            uchar4 u;
            u.x = (uint8_t)s[(c0 + 0) * (HW + 1) + w];
            u.y = (uint8_t)s[(c0 + 1) * (HW + 1) + w];
            u.z = (uint8_t)s[(c0 + 2) * (HW + 1) + w];
            u.w = (uint8_t)s[(c0 + 3) * (HW + 1) + w];
            word = *(uint32_t*)&u;
        }
        ((uint32_t*)dst)[i] = word;
    }
}

// ---------------- persistent implicit-im2col GEMM ----------------
__global__ void __launch_bounds__(THREADS, 3)
gemm_kernel(const void* __restrict__ bias, void* __restrict__ outv) {
    extern __shared__ char smem[];
    const uint32_t smb = smem_to_u32(smem);
    const int tid  = threadIdx.x;
    const int lane = tid & 31;
    const int wrp  = tid >> 5;
    const int wm   = wrp & 3;      // warp M (0..3), 32 rows
    const int wn   = wrp >> 2;     // warp N (0..1), 16 cols
    const int flag = g_flag;

    const int rowA0 = tid >> 2;           // 0..63
    const int rowA1 = rowA0 + 64;
    const int c16   = tid & 3;
    const int planeB = tid >> 7;          // 0..1
    const int rowB   = (tid >> 2) & 31;   // 0..31

    const uint32_t sA0 = smb + rowA0 * PITCH + c16 * 16;
    const uint32_t sA1 = smb + rowA1 * PITCH + c16 * 16;
    const uint32_t sBw = smb + SM_TILE_A + planeB * SM_TILE_B + rowB * PITCH + c16 * 16;

    for (int tile = blockIdx.x; tile < NTILE_TOT; tile += GRIDP) {
        const int mt = tile >> 3;
        const int nt = tile & 7;

        auto arow_ptr = [&](int r) -> const int8_t* {
            int p_ = mt * CTA_M + r;
            int n_ = p_ / HW2;
            int hw_ = p_ - n_ * HW2;
            int h_ = hw_ / HW;
            int w_ = hw_ - h_ * HW;
            return g_Xt + ((size_t)((n_ * PHW + h_ + 1) * PHW + (w_ + 1))) * CIN + c16 * 16;
        };
        const int8_t* Arow0 = arow_ptr(rowA0);
        const int8_t* Arow1 = arow_ptr(rowA1);
        const int8_t* Wb = g_W + (size_t)planeB * COUT * KDIM
                           + (size_t)(nt * CTA_N + rowB) * KDIM + c16 * 16;

        int acch[2][2][4];
        int accl[2][2][4];
#pragma unroll
        for (int mb = 0; mb < 2; mb++)
#pragma unroll
            for (int q = 0; q < 2; q++)
#pragma unroll
                for (int i = 0; i < 4; i++) { acch[mb][q][i] = 0; accl[mb][q][i] = 0; }

        auto load_chunk = [&](int kc, int buf) {
            int khkw = kc >> 1;
            int kh = khkw / 3;
            int kw = khkw - kh * 3;
            int off = ((kh - 1) * PHW + (kw - 1)) * CIN + (kc & 1) * KC;
            uint32_t sb = buf * SM_STAGE;
            cp16(sA0 + sb, Arow0 + off);
            cp16(sA1 + sb, Arow1 + off);
            cp16(sBw + sb, Wb + kc * KC);
        };

        __syncthreads();   // previous tile's smem reads complete before refill

#pragma unroll
        for (int s = 0; s < STAGES - 1; s++) { load_chunk(s, s); CP_COMMIT(); }

        for (int kc = 0; kc < NCHUNK; kc++) {
            CP_WAIT(STAGES - 2);
            __syncthreads();
            {
                int nk = kc + STAGES - 1;
                if (nk < NCHUNK) load_chunk(nk, nk & (STAGES - 1));
                CP_COMMIT();
            }

            const uint32_t smA  = smb + (kc & (STAGES - 1)) * SM_STAGE;
            const uint32_t smBh = smA + SM_TILE_A;
            const uint32_t smBl = smBh + SM_TILE_B;

#pragma unroll
            for (int ks = 0; ks < 2; ks++) {
                uint32_t a[2][4];
#pragma unroll
                for (int mb = 0; mb < 2; mb++) {
                    uint32_t addr = smA + (uint32_t)((wm * 32 + mb * 16 + (lane & 15)) * PITCH
                                                     + (ks * 2 + (lane >> 4)) * 16);
                    ldsm_x4(a[mb], addr);
                }
                uint32_t bh[4], bl[4];
                {
                    uint32_t boff = (uint32_t)((wn * 16 + (lane & 7) + ((lane >> 4) << 3)) * PITCH
                                               + (ks * 2 + ((lane >> 3) & 1)) * 16);
                    ldsm_x4(bh, smBh + boff);
                    ldsm_x4(bl, smBl + boff);
                }
#pragma unroll
                for (int mb = 0; mb < 2; mb++)
#pragma unroll
                    for (int q = 0; q < 2; q++) {
                        mma_s8s8(acch[mb][q], a[mb], &bh[q * 2]);
                        mma_s8u8(accl[mb][q], a[mb], &bl[q * 2]);
                    }
            }
        }

        // ---- epilogue ----
        const int co_b = nt * CTA_N + wn * 16 + (lane & 3) * 2;
        long long bset[2][2];   // [q][i&1]
#pragma unroll
        for (int q = 0; q < 2; q++) {
            bset[q][0] = load_val(bias, co_b + q * 8, flag);
            bset[q][1] = load_val(bias, co_b + q * 8 + 1, flag);
        }
#pragma unroll
        for (int mb = 0; mb < 2; mb++) {
#pragma unroll
            for (int q = 0; q < 2; q++) {
                int p0  = mt * CTA_M + wm * 32 + mb * 16 + (lane >> 2);
                int co0 = co_b + q * 8;
#pragma unroll
                for (int i = 0; i < 4; i++) {
                    int p  = p0 + ((i >= 2) ? 8 : 0);
                    int co = co0 + (i & 1);
                    long long v = (((long long)acch[mb][q][i] << 8)
                                   + (long long)accl[mb][q][i] + bset[q][i & 1]) >> SHIFT;
                    int n  = p / HW2;
                    int hw = p - n * HW2;
                    size_t oi = ((size_t)(n * COUT + co)) * HW2 + hw;
                    if (flag == FLAG_I64)      ((long long*)outv)[oi] = v;
                    else if (flag == FLAG_F64) ((double*)outv)[oi] = (double)v;
                    else                       ((float*)outv)[oi] = (float)v;
                }
            }
        }
    }
}

// ---------------- launch ----------------
extern "C" void kernel_launch(void* const* d_in, const int* in_sizes, int n_in,
                              void* d_out, int out_size) {
    const void* x = nullptr; const void* wq = nullptr; const void* bias = nullptr;
    for (int i = 0; i < n_in; i++) {
        if (in_sizes[i] == NB * CIN * HW2)      x    = d_in[i];
        else if (in_sizes[i] == COUT * KDIM)    wq   = d_in[i];
        else if (in_sizes[i] == COUT)           bias = d_in[i];
    }
    (void)out_size;

    detect_kernel<<<1, 32>>>(x);
    prep_kernel<<<TR_BLOCKS + PW_BLOCKS, 256>>>(x, wq);

    cudaFuncSetAttribute(gemm_kernel, cudaFuncAttributeMaxDynamicSharedMemorySize, SM_TOTAL);
    gemm_kernel<<<GRIDP, THREADS, SM_TOTAL>>>(bias, d_out);
}